// round 10
// baseline (speedup 1.0000x reference)
#include <cuda_runtime.h>
#include <math.h>

typedef unsigned int u32;
typedef unsigned long long u64;

#define NLEV 16
#define HSIZE (1u << 19)
#define HMASK (HSIZE - 1u)
#define NPTS (4096 * 128)
#define NCHUNK 4
#define CPTS (NPTS / NCHUNK)

struct Consts { float res[NLEV]; };

// 67 MB scratch: per-level encoded features, feat-major for coalescing.
__device__ float2 g_enc[NLEV * NPTS];

// ---------- packed f32x2 helpers ----------
__device__ __forceinline__ u64 pk2(float a, float b) {
    u64 r; asm("mov.b64 %0,{%1,%2};" : "=l"(r) : "f"(a), "f"(b)); return r;
}
__device__ __forceinline__ void up2(u64 v, float& a, float& b) {
    asm("mov.b64 {%0,%1},%2;" : "=f"(a), "=f"(b) : "l"(v));
}
__device__ __forceinline__ u64 f2fma(u64 a, u64 b, u64 c) {
    u64 d; asm("fma.rn.f32x2 %0,%1,%2,%3;" : "=l"(d) : "l"(a), "l"(b), "l"(c)); return d;
}

// ===================== K1: encode (gather-bound) =====================

__device__ __forceinline__ void level_fetch(
    float px, float py, float pz, float r,
    const float2* __restrict__ tab,
    float2 tv[8], float& ax, float& ay, float& az)
{
    const float X = px * r, Y = py * r, Z = pz * r;
    const float fx = floorf(X), fy = floorf(Y), fz = floorf(Z);
    ax = X - fx; ay = Y - fy; az = Z - fz;
    const u32 ix = (u32)fx, iy = (u32)fy, iz = (u32)fz;
    const u32 hx0 = ix, hx1 = ix + 1u;
    const u32 hy0 = iy * 2654435761u, hy1 = hy0 + 2654435761u;
    const u32 hz0 = iz * 805459861u,  hz1 = hz0 + 805459861u;
    #pragma unroll
    for (int c = 0; c < 8; c++) {
        const u32 hx = (c & 4) ? hx1 : hx0;
        const u32 hy = (c & 2) ? hy1 : hy0;
        const u32 hz = (c & 1) ? hz1 : hz0;
        tv[c] = __ldg(tab + ((hx ^ hy ^ hz) & HMASK));
    }
}

__global__ void __launch_bounds__(256, 3) encode_kernel(
    const float* __restrict__ xyz, const float* __restrict__ table, Consts cc,
    int base)
{
    const int p = base + blockIdx.x * 256 + threadIdx.x;
    const float px = __ldg(xyz + 3 * p);
    const float py = __ldg(xyz + 3 * p + 1);
    const float pz = __ldg(xyz + 3 * p + 2);

    float2 tvb[2][8];
    float fr[2][3];
    level_fetch(px, py, pz, cc.res[0], (const float2*)table,
                tvb[0], fr[0][0], fr[0][1], fr[0][2]);

    #pragma unroll 2
    for (int l = 0; l < NLEV; l++) {
        const int cur = l & 1, nxt = cur ^ 1;
        if (l + 1 < NLEV)
            level_fetch(px, py, pz, cc.res[l + 1],
                        (const float2*)table + (size_t)(l + 1) * HSIZE,
                        tvb[nxt], fr[nxt][0], fr[nxt][1], fr[nxt][2]);
        const float ax = fr[cur][0], ay = fr[cur][1], az = fr[cur][2];
        const float bx = 1.f - ax, by = 1.f - ay, bz = 1.f - az;
        float a0 = 0.f, a1 = 0.f;
        #pragma unroll
        for (int c = 0; c < 8; c++) {
            const float w = ((c & 4) ? ax : bx) * ((c & 2) ? ay : by) * ((c & 1) ? az : bz);
            a0 = fmaf(w, tvb[cur][c].x, a0);
            a1 = fmaf(w, tvb[cur][c].y, a1);
        }
        g_enc[l * NPTS + p] = make_float2(a0, a1);
    }
}

// ===================== K2: MLP + volrend (FMA-bound) =====================

#define OFF_WIN  0
#define OFF_WOUT 2048
#define OFF_W1   3072
#define OFF_W2   4032
#define OFF_W3   8128
#define OFF_FA   8320                 // feats ray A: 128 rows x 17
#define OFF_FB   (8320 + 128 * 17)
#define SMEM_FLOATS (8320 + 2 * 128 * 17)
#define SMEM_BYTES (SMEM_FLOATS * 4)

__global__ void __launch_bounds__(128, 4) mlp_kernel(
    const float* __restrict__ delta,
    const float* __restrict__ w_in, const float* __restrict__ w_out,
    const float* __restrict__ rw1, const float* __restrict__ rw2,
    const float* __restrict__ rw3, float4* __restrict__ out, float offset,
    int base)
{
    extern __shared__ float dsm[];
    __shared__ float wsumA[4], wsumB[4];
    const int t = threadIdx.x;
    for (int i = t; i < 8320; i += 128) {
        float v;
        if (i < 2048)      v = w_in[i];
        else if (i < 3072) v = w_out[i - 2048];
        else if (i < 4032) v = rw1[i - 3072];
        else if (i < 8128) v = rw2[i - 4032];
        else               v = rw3[i - 8128];
        dsm[i] = v;
    }
    __syncthreads();

    const int pA = base + blockIdx.x * 256 + t;   // ray A
    const int pB = pA + 128;                      // ray B
    float* FA = dsm + OFF_FA + t * 17;
    float* FB = dsm + OFF_FB + t * 17;

    // ---- density MLP: two passes over hidden-halves, low register peak ----
    u64 rA2[8], rB2[8];
    #pragma unroll
    for (int j = 0; j < 8; j++) { rA2[j] = 0ULL; rB2[j] = 0ULL; }

    #pragma unroll 1
    for (int half = 0; half < 2; half++) {
        u64 hA[16], hB[16];
        #pragma unroll
        for (int j = 0; j < 16; j++) { hA[j] = 0ULL; hB[j] = 0ULL; }

        #pragma unroll 1
        for (int l = 0; l < NLEV; l++) {
            const float2 eA = g_enc[l * NPTS + pA];
            const float2 eB = g_enc[l * NPTS + pB];
            const u64 e0A = pk2(eA.x, eA.x), e1A = pk2(eA.y, eA.y);
            const u64 e0B = pk2(eB.x, eB.x), e1B = pk2(eB.y, eB.y);
            const u64* r0 = (const u64*)(dsm + OFF_WIN + (2 * l) * 64 + half * 32);
            const u64* r1 = r0 + 32;
            #pragma unroll
            for (int j = 0; j < 16; j += 2) {
                const ulonglong2 wv0 = *(const ulonglong2*)(r0 + j);
                const ulonglong2 wv1 = *(const ulonglong2*)(r1 + j);
                hA[j]     = f2fma(e1A, wv1.x, f2fma(e0A, wv0.x, hA[j]));
                hA[j + 1] = f2fma(e1A, wv1.y, f2fma(e0A, wv0.y, hA[j + 1]));
                hB[j]     = f2fma(e1B, wv1.x, f2fma(e0B, wv0.x, hB[j]));
                hB[j + 1] = f2fma(e1B, wv1.y, f2fma(e0B, wv0.y, hB[j + 1]));
            }
        }

        #pragma unroll
        for (int ic = 0; ic < 16; ic++) {
            float vA0, vA1, vB0, vB1;
            up2(hA[ic], vA0, vA1); up2(hB[ic], vB0, vB1);
            const u64 e0A = pk2(fmaxf(vA0, 0.f), fmaxf(vA0, 0.f));
            const u64 e1A = pk2(fmaxf(vA1, 0.f), fmaxf(vA1, 0.f));
            const u64 e0B = pk2(fmaxf(vB0, 0.f), fmaxf(vB0, 0.f));
            const u64 e1B = pk2(fmaxf(vB1, 0.f), fmaxf(vB1, 0.f));
            const u64* r0 = (const u64*)(dsm + OFF_WOUT + (half * 32 + 2 * ic) * 16);
            const u64* r1 = r0 + 8;
            #pragma unroll
            for (int j = 0; j < 8; j += 2) {
                const ulonglong2 wv0 = *(const ulonglong2*)(r0 + j);
                const ulonglong2 wv1 = *(const ulonglong2*)(r1 + j);
                rA2[j]     = f2fma(e1A, wv1.x, f2fma(e0A, wv0.x, rA2[j]));
                rA2[j + 1] = f2fma(e1A, wv1.y, f2fma(e0A, wv0.y, rA2[j + 1]));
                rB2[j]     = f2fma(e1B, wv1.x, f2fma(e0B, wv0.x, rB2[j]));
                rB2[j + 1] = f2fma(e1B, wv1.y, f2fma(e0B, wv0.y, rB2[j + 1]));
            }
        }
    }

    // unpack raw: raw[0] -> density; raw[1..15] -> feats in smem rows
    float d0A = 0.f, d0B = 0.f;
    #pragma unroll
    for (int j = 0; j < 8; j++) {
        float vA0, vA1, vB0, vB1;
        up2(rA2[j], vA0, vA1); up2(rB2[j], vB0, vB1);
        const int o = 2 * j;
        if (o == 0) { d0A = vA0; d0B = vB0; }
        else { FA[o - 1] = vA0; FB[o - 1] = vB0; }
        FA[o] = vA1; FB[o] = vB1;
    }

    // ---- volume-rendering weights: block-wide exclusive scan per ray ----
    const float ddA = expf(d0A + offset + logf(__ldg(delta + pA)));
    const float ddB = expf(d0B + offset + logf(__ldg(delta + pB)));
    float sA = ddA, sB = ddB;
    const int lane = t & 31, wid = t >> 5;
    #pragma unroll
    for (int o = 1; o < 32; o <<= 1) {
        const float vA = __shfl_up_sync(0xffffffffu, sA, o);
        const float vB = __shfl_up_sync(0xffffffffu, sB, o);
        if (lane >= o) { sA += vA; sB += vB; }
    }
    if (lane == 31) { wsumA[wid] = sA; wsumB[wid] = sB; }
    __syncthreads();
    float prefA = 0.f, prefB = 0.f;
    #pragma unroll
    for (int w = 0; w < 3; w++)
        if (wid > w) { prefA += wsumA[w]; prefB += wsumB[w]; }
    const float wgtA = (1.f - expf(-ddA)) * expf(-(prefA + sA - ddA));
    const float wgtB = (1.f - expf(-ddB)) * expf(-(prefB + sB - ddB));

    // ---- rgb MLP: per point (A then B) to halve the register peak ----
    #pragma unroll 1
    for (int pt = 0; pt < 2; pt++) {
        const float* F = (pt == 0) ? FA : FB;

        u64 h1[32];
        #pragma unroll
        for (int j = 0; j < 32; j++) h1[j] = 0ULL;
        #pragma unroll 1
        for (int i = 0; i < 15; i++) {
            const float f = F[i];
            const u64 e = pk2(f, f);
            const u64* row = (const u64*)(dsm + OFF_W1 + i * 64);
            #pragma unroll
            for (int j = 0; j < 32; j += 2) {
                const ulonglong2 wv = *(const ulonglong2*)(row + j);
                h1[j]     = f2fma(e, wv.x, h1[j]);
                h1[j + 1] = f2fma(e, wv.y, h1[j + 1]);
            }
        }
        #pragma unroll
        for (int j = 0; j < 32; j++) {
            float v0, v1; up2(h1[j], v0, v1);
            h1[j] = pk2(fmaxf(v0, 0.f), fmaxf(v1, 0.f));
        }

        float cr = 0.f, cg = 0.f, cb = 0.f;
        #pragma unroll 1
        for (int ob = 0; ob < 8; ob++) {
            u64 acc[4];
            #pragma unroll
            for (int j = 0; j < 4; j++) acc[j] = 0ULL;
            #pragma unroll
            for (int ic = 0; ic < 32; ic++) {
                float v0, v1; up2(h1[ic], v0, v1);
                const u64 e0 = pk2(v0, v0), e1 = pk2(v1, v1);
                const u64* r0 = (const u64*)(dsm + OFF_W2 + (2 * ic) * 64 + ob * 8);
                const u64* r1 = r0 + 32;
                #pragma unroll
                for (int j = 0; j < 4; j += 2) {
                    const ulonglong2 wv0 = *(const ulonglong2*)(r0 + j);
                    const ulonglong2 wv1 = *(const ulonglong2*)(r1 + j);
                    acc[j]     = f2fma(e1, wv1.x, f2fma(e0, wv0.x, acc[j]));
                    acc[j + 1] = f2fma(e1, wv1.y, f2fma(e0, wv0.y, acc[j + 1]));
                }
            }
            #pragma unroll
            for (int j = 0; j < 4; j++) {
                float v0, v1; up2(acc[j], v0, v1);
                v0 = fmaxf(v0, 0.f); v1 = fmaxf(v1, 0.f);
                const float* q = dsm + OFF_W3 + (ob * 8 + 2 * j) * 3;
                cr = fmaf(v0, q[0], fmaf(v1, q[3], cr));
                cg = fmaf(v0, q[1], fmaf(v1, q[4], cg));
                cb = fmaf(v0, q[2], fmaf(v1, q[5], cb));
            }
        }

        const float wgt = (pt == 0) ? wgtA : wgtB;
        out[(pt == 0) ? pA : pB] =
            make_float4(wgt, 1.f / (1.f + expf(-cr)),
                        1.f / (1.f + expf(-cg)), 1.f / (1.f + expf(-cb)));
    }
}

extern "C" void kernel_launch(void* const* d_in, const int* in_sizes, int n_in,
                              void* d_out, int out_size)
{
    const float* xyz   = (const float*)d_in[0];
    const float* delta = (const float*)d_in[1];
    const float* table = (const float*)d_in[2];
    const float* w_in  = (const float*)d_in[3];
    const float* w_out = (const float*)d_in[4];
    const float* rw1   = (const float*)d_in[5];
    const float* rw2   = (const float*)d_in[6];
    const float* rw3   = (const float*)d_in[7];
    float4* out = (float4*)d_out;

    Consts cc;
    const double scale = exp((log(4096.0) - log(16.0)) / 15.0);
    for (int l = 0; l < NLEV; l++)
        cc.res[l] = (float)floor(16.0 * pow(scale, (double)l));
    const float offset = (float)(log(log(1.0 / 0.99)) - log(6.0 - 2.0) - 0.5);

    // streams/events created once, on the (uncaptured) correctness call
    static cudaStream_t s2 = 0;
    static cudaEvent_t evFork = 0, evJoin = 0, evC[NCHUNK];
    static int inited = 0;
    if (!inited) {
        cudaStreamCreateWithFlags(&s2, cudaStreamNonBlocking);
        cudaEventCreateWithFlags(&evFork, cudaEventDisableTiming);
        cudaEventCreateWithFlags(&evJoin, cudaEventDisableTiming);
        for (int i = 0; i < NCHUNK; i++)
            cudaEventCreateWithFlags(&evC[i], cudaEventDisableTiming);
        cudaFuncSetAttribute(mlp_kernel,
                             cudaFuncAttributeMaxDynamicSharedMemorySize,
                             SMEM_BYTES);
        inited = 1;
    }

    // chunked two-stream pipeline: K1 (gathers, stream 0) overlaps K2
    // (MLP, s2) of the previous chunk. Event edges are graph-capturable.
    cudaEventRecord(evFork, 0);
    cudaStreamWaitEvent(s2, evFork, 0);
    for (int c = 0; c < NCHUNK; c++) {
        encode_kernel<<<CPTS / 256, 256>>>(xyz, table, cc, c * CPTS);
        cudaEventRecord(evC[c], 0);
        cudaStreamWaitEvent(s2, evC[c], 0);
        mlp_kernel<<<CPTS / 256, 128, SMEM_BYTES, s2>>>(
            delta, w_in, w_out, rw1, rw2, rw3, out, offset, c * CPTS);
    }
    cudaEventRecord(evJoin, s2);
    cudaStreamWaitEvent(0, evJoin, 0);
}

// round 11
// speedup vs baseline: 1.6719x; 1.6719x over previous
#include <cuda_runtime.h>
#include <math.h>

typedef unsigned int u32;
typedef unsigned long long u64;

#define NLEV 16
#define HSIZE (1u << 19)
#define HMASK (HSIZE - 1u)
#define NPTS (4096 * 128)

struct Consts { float res[NLEV]; };

// 67 MB scratch: per-level encoded features, feat-major for coalescing.
__device__ float2 g_enc[NLEV * NPTS];

// ---------- packed f32x2 helpers ----------
__device__ __forceinline__ u64 pk2(float a, float b) {
    u64 r; asm("mov.b64 %0,{%1,%2};" : "=l"(r) : "f"(a), "f"(b)); return r;
}
__device__ __forceinline__ void up2(u64 v, float& a, float& b) {
    asm("mov.b64 {%0,%1},%2;" : "=f"(a), "=f"(b) : "l"(v));
}
__device__ __forceinline__ u64 f2fma(u64 a, u64 b, u64 c) {
    u64 d; asm("fma.rn.f32x2 %0,%1,%2,%3;" : "=l"(d) : "l"(a), "l"(b), "l"(c)); return d;
}

// ===================== K1: encode (gather-bound) =====================

__device__ __forceinline__ void level_fetch(
    float px, float py, float pz, float r,
    const float2* __restrict__ tab,
    float2 tv[8], float& ax, float& ay, float& az)
{
    const float X = px * r, Y = py * r, Z = pz * r;
    const float fx = floorf(X), fy = floorf(Y), fz = floorf(Z);
    ax = X - fx; ay = Y - fy; az = Z - fz;
    const u32 ix = (u32)fx, iy = (u32)fy, iz = (u32)fz;
    const u32 hx0 = ix, hx1 = ix + 1u;
    const u32 hy0 = iy * 2654435761u, hy1 = hy0 + 2654435761u;
    const u32 hz0 = iz * 805459861u,  hz1 = hz0 + 805459861u;
    #pragma unroll
    for (int c = 0; c < 8; c++) {
        const u32 hx = (c & 4) ? hx1 : hx0;
        const u32 hy = (c & 2) ? hy1 : hy0;
        const u32 hz = (c & 1) ? hz1 : hz0;
        tv[c] = __ldg(tab + ((hx ^ hy ^ hz) & HMASK));
    }
}

__global__ void __launch_bounds__(256, 4) encode_kernel(
    const float* __restrict__ xyz, const float* __restrict__ table, Consts cc)
{
    const int p = blockIdx.x * 256 + threadIdx.x;
    const float px = __ldg(xyz + 3 * p);
    const float py = __ldg(xyz + 3 * p + 1);
    const float pz = __ldg(xyz + 3 * p + 2);

    float2 tvb[2][8];
    float fr[2][3];
    level_fetch(px, py, pz, cc.res[0], (const float2*)table,
                tvb[0], fr[0][0], fr[0][1], fr[0][2]);

    #pragma unroll 2
    for (int l = 0; l < NLEV; l++) {
        const int cur = l & 1, nxt = cur ^ 1;
        if (l + 1 < NLEV)
            level_fetch(px, py, pz, cc.res[l + 1],
                        (const float2*)table + (size_t)(l + 1) * HSIZE,
                        tvb[nxt], fr[nxt][0], fr[nxt][1], fr[nxt][2]);
        const float ax = fr[cur][0], ay = fr[cur][1], az = fr[cur][2];
        const float bx = 1.f - ax, by = 1.f - ay, bz = 1.f - az;
        float a0 = 0.f, a1 = 0.f;
        #pragma unroll
        for (int c = 0; c < 8; c++) {
            const float w = ((c & 4) ? ax : bx) * ((c & 2) ? ay : by) * ((c & 1) ? az : bz);
            a0 = fmaf(w, tvb[cur][c].x, a0);
            a1 = fmaf(w, tvb[cur][c].y, a1);
        }
        g_enc[l * NPTS + p] = make_float2(a0, a1);
    }
}

// ===================== K2: MLP + volrend (FMA-bound) =====================

#define OFF_WIN  0
#define OFF_WOUT 2048
#define OFF_W1   3072
#define OFF_W2   4032
#define OFF_W3   8128
#define OFF_FA   8320                 // feats ray A: 128 rows x 17
#define OFF_FB   (8320 + 128 * 17)
#define SMEM_FLOATS (8320 + 2 * 128 * 17)
#define SMEM_BYTES (SMEM_FLOATS * 4)

__global__ void __launch_bounds__(128, 4) mlp_kernel(
    const float* __restrict__ delta,
    const float* __restrict__ w_in, const float* __restrict__ w_out,
    const float* __restrict__ rw1, const float* __restrict__ rw2,
    const float* __restrict__ rw3, float4* __restrict__ out, float offset)
{
    extern __shared__ float dsm[];
    __shared__ float wsumA[4], wsumB[4];
    const int t = threadIdx.x;
    for (int i = t; i < 8320; i += 128) {
        float v;
        if (i < 2048)      v = w_in[i];
        else if (i < 3072) v = w_out[i - 2048];
        else if (i < 4032) v = rw1[i - 3072];
        else if (i < 8128) v = rw2[i - 4032];
        else               v = rw3[i - 8128];
        dsm[i] = v;
    }
    __syncthreads();

    const int pA = blockIdx.x * 256 + t;   // ray A
    const int pB = pA + 128;               // ray B
    float* FA = dsm + OFF_FA + t * 17;
    float* FB = dsm + OFF_FB + t * 17;

    // ---- density MLP: two passes over hidden-halves, low register peak ----
    u64 rA2[8], rB2[8];
    #pragma unroll
    for (int j = 0; j < 8; j++) { rA2[j] = 0ULL; rB2[j] = 0ULL; }

    #pragma unroll 1
    for (int half = 0; half < 2; half++) {
        u64 hA[16], hB[16];
        #pragma unroll
        for (int j = 0; j < 16; j++) { hA[j] = 0ULL; hB[j] = 0ULL; }

        #pragma unroll 1
        for (int l = 0; l < NLEV; l++) {
            const float2 eA = g_enc[l * NPTS + pA];
            const float2 eB = g_enc[l * NPTS + pB];
            const u64 e0A = pk2(eA.x, eA.x), e1A = pk2(eA.y, eA.y);
            const u64 e0B = pk2(eB.x, eB.x), e1B = pk2(eB.y, eB.y);
            const u64* r0 = (const u64*)(dsm + OFF_WIN + (2 * l) * 64 + half * 32);
            const u64* r1 = r0 + 32;
            #pragma unroll
            for (int j = 0; j < 16; j += 2) {
                const ulonglong2 wv0 = *(const ulonglong2*)(r0 + j);
                const ulonglong2 wv1 = *(const ulonglong2*)(r1 + j);
                hA[j]     = f2fma(e1A, wv1.x, f2fma(e0A, wv0.x, hA[j]));
                hA[j + 1] = f2fma(e1A, wv1.y, f2fma(e0A, wv0.y, hA[j + 1]));
                hB[j]     = f2fma(e1B, wv1.x, f2fma(e0B, wv0.x, hB[j]));
                hB[j + 1] = f2fma(e1B, wv1.y, f2fma(e0B, wv0.y, hB[j + 1]));
            }
        }

        #pragma unroll
        for (int ic = 0; ic < 16; ic++) {
            float vA0, vA1, vB0, vB1;
            up2(hA[ic], vA0, vA1); up2(hB[ic], vB0, vB1);
            const u64 e0A = pk2(fmaxf(vA0, 0.f), fmaxf(vA0, 0.f));
            const u64 e1A = pk2(fmaxf(vA1, 0.f), fmaxf(vA1, 0.f));
            const u64 e0B = pk2(fmaxf(vB0, 0.f), fmaxf(vB0, 0.f));
            const u64 e1B = pk2(fmaxf(vB1, 0.f), fmaxf(vB1, 0.f));
            const u64* r0 = (const u64*)(dsm + OFF_WOUT + (half * 32 + 2 * ic) * 16);
            const u64* r1 = r0 + 8;
            #pragma unroll
            for (int j = 0; j < 8; j += 2) {
                const ulonglong2 wv0 = *(const ulonglong2*)(r0 + j);
                const ulonglong2 wv1 = *(const ulonglong2*)(r1 + j);
                rA2[j]     = f2fma(e1A, wv1.x, f2fma(e0A, wv0.x, rA2[j]));
                rA2[j + 1] = f2fma(e1A, wv1.y, f2fma(e0A, wv0.y, rA2[j + 1]));
                rB2[j]     = f2fma(e1B, wv1.x, f2fma(e0B, wv0.x, rB2[j]));
                rB2[j + 1] = f2fma(e1B, wv1.y, f2fma(e0B, wv0.y, rB2[j + 1]));
            }
        }
    }

    // unpack raw: raw[0] -> density; raw[1..15] -> feats in smem rows
    float d0A = 0.f, d0B = 0.f;
    #pragma unroll
    for (int j = 0; j < 8; j++) {
        float vA0, vA1, vB0, vB1;
        up2(rA2[j], vA0, vA1); up2(rB2[j], vB0, vB1);
        const int o = 2 * j;
        if (o == 0) { d0A = vA0; d0B = vB0; }
        else { FA[o - 1] = vA0; FB[o - 1] = vB0; }
        FA[o] = vA1; FB[o] = vB1;
    }

    // ---- volume-rendering weights: block-wide exclusive scan per ray ----
    const float ddA = expf(d0A + offset + logf(__ldg(delta + pA)));
    const float ddB = expf(d0B + offset + logf(__ldg(delta + pB)));
    float sA = ddA, sB = ddB;
    const int lane = t & 31, wid = t >> 5;
    #pragma unroll
    for (int o = 1; o < 32; o <<= 1) {
        const float vA = __shfl_up_sync(0xffffffffu, sA, o);
        const float vB = __shfl_up_sync(0xffffffffu, sB, o);
        if (lane >= o) { sA += vA; sB += vB; }
    }
    if (lane == 31) { wsumA[wid] = sA; wsumB[wid] = sB; }
    __syncthreads();
    float prefA = 0.f, prefB = 0.f;
    #pragma unroll
    for (int w = 0; w < 3; w++)
        if (wid > w) { prefA += wsumA[w]; prefB += wsumB[w]; }
    const float wgtA = (1.f - expf(-ddA)) * expf(-(prefA + sA - ddA));
    const float wgtB = (1.f - expf(-ddB)) * expf(-(prefB + sB - ddB));

    // ---- rgb MLP: per point (A then B) to halve the register peak ----
    #pragma unroll 1
    for (int pt = 0; pt < 2; pt++) {
        const float* F = (pt == 0) ? FA : FB;

        u64 h1[32];
        #pragma unroll
        for (int j = 0; j < 32; j++) h1[j] = 0ULL;
        #pragma unroll 1
        for (int i = 0; i < 15; i++) {
            const float f = F[i];
            const u64 e = pk2(f, f);
            const u64* row = (const u64*)(dsm + OFF_W1 + i * 64);
            #pragma unroll
            for (int j = 0; j < 32; j += 2) {
                const ulonglong2 wv = *(const ulonglong2*)(row + j);
                h1[j]     = f2fma(e, wv.x, h1[j]);
                h1[j + 1] = f2fma(e, wv.y, h1[j + 1]);
            }
        }
        #pragma unroll
        for (int j = 0; j < 32; j++) {
            float v0, v1; up2(h1[j], v0, v1);
            h1[j] = pk2(fmaxf(v0, 0.f), fmaxf(v1, 0.f));
        }

        float cr = 0.f, cg = 0.f, cb = 0.f;
        #pragma unroll 1
        for (int ob = 0; ob < 8; ob++) {
            u64 acc[4];
            #pragma unroll
            for (int j = 0; j < 4; j++) acc[j] = 0ULL;
            #pragma unroll
            for (int ic = 0; ic < 32; ic++) {
                float v0, v1; up2(h1[ic], v0, v1);
                const u64 e0 = pk2(v0, v0), e1 = pk2(v1, v1);
                const u64* r0 = (const u64*)(dsm + OFF_W2 + (2 * ic) * 64 + ob * 8);
                const u64* r1 = r0 + 32;
                #pragma unroll
                for (int j = 0; j < 4; j += 2) {
                    const ulonglong2 wv0 = *(const ulonglong2*)(r0 + j);
                    const ulonglong2 wv1 = *(const ulonglong2*)(r1 + j);
                    acc[j]     = f2fma(e1, wv1.x, f2fma(e0, wv0.x, acc[j]));
                    acc[j + 1] = f2fma(e1, wv1.y, f2fma(e0, wv0.y, acc[j + 1]));
                }
            }
            #pragma unroll
            for (int j = 0; j < 4; j++) {
                float v0, v1; up2(acc[j], v0, v1);
                v0 = fmaxf(v0, 0.f); v1 = fmaxf(v1, 0.f);
                const float* q = dsm + OFF_W3 + (ob * 8 + 2 * j) * 3;
                cr = fmaf(v0, q[0], fmaf(v1, q[3], cr));
                cg = fmaf(v0, q[1], fmaf(v1, q[4], cg));
                cb = fmaf(v0, q[2], fmaf(v1, q[5], cb));
            }
        }

        const float wgt = (pt == 0) ? wgtA : wgtB;
        out[(pt == 0) ? pA : pB] =
            make_float4(wgt, 1.f / (1.f + expf(-cr)),
                        1.f / (1.f + expf(-cg)), 1.f / (1.f + expf(-cb)));
    }
}

extern "C" void kernel_launch(void* const* d_in, const int* in_sizes, int n_in,
                              void* d_out, int out_size)
{
    const float* xyz   = (const float*)d_in[0];
    const float* delta = (const float*)d_in[1];
    const float* table = (const float*)d_in[2];
    const float* w_in  = (const float*)d_in[3];
    const float* w_out = (const float*)d_in[4];
    const float* rw1   = (const float*)d_in[5];
    const float* rw2   = (const float*)d_in[6];
    const float* rw3   = (const float*)d_in[7];
    float4* out = (float4*)d_out;

    Consts cc;
    const double scale = exp((log(4096.0) - log(16.0)) / 15.0);
    for (int l = 0; l < NLEV; l++)
        cc.res[l] = (float)floor(16.0 * pow(scale, (double)l));
    const float offset = (float)(log(log(1.0 / 0.99)) - log(6.0 - 2.0) - 0.5);

    static int inited = 0;
    if (!inited) {
        cudaFuncSetAttribute(mlp_kernel,
                             cudaFuncAttributeMaxDynamicSharedMemorySize,
                             SMEM_BYTES);
        inited = 1;
    }

    // sequential full-grid split: K1 gather-bound at 32 warps/SM,
    // K2 FMA-bound at 16 warps/SM. (launch idx 5 under ncu = mlp_kernel)
    encode_kernel<<<NPTS / 256, 256>>>(xyz, table, cc);
    mlp_kernel<<<NPTS / 256, 128, SMEM_BYTES>>>(delta, w_in, w_out,
                                                rw1, rw2, rw3, out, offset);
}